// round 5
// baseline (speedup 1.0000x reference)
#include <cuda_runtime.h>
#include <math.h>
#include <stdint.h>

// ---------------- problem constants ----------------
#define NTOT   102400          // B*T*NODES
#define ETOT   1638400         // edges
#define BATCH  8
#define TSTEPS 32
#define NODES  400
#define NSEQ   (BATCH*NODES)   // 3200
#define D_IN   64
#define L1F    96
#define L2F    64
#define GATES  256             // 4*64
#define FC1F   128
#define FC2F   3

// ---------------- device scratch (static: allowed) ----------------
__device__ float g_colsum[64];
__device__ float g_colsumsq[64];
__device__ float g_mean[64];
__device__ float g_rstd[64];
__device__ int   g_counts[NTOT];
__device__ int   g_rowptr[NTOT + 1];
__device__ int   g_cursor[NTOT];
__device__ int   g_bsums[128];
__device__ float g_deg[NTOT];
__device__ float g_dis[NTOT];
__device__ int   g_csrsrc[ETOT];
__device__ float g_csrw[ETOT];
__device__ float g_h1pre[(size_t)NTOT * L1F];
__device__ float g_h1   [(size_t)NTOT * L1F];
__device__ float g_h2pre[(size_t)NTOT * L2F];
__device__ float g_h2   [(size_t)NTOT * L2F];
__device__ float g_xg   [(size_t)NTOT * GATES];
__device__ float g_hfin [(size_t)NSEQ * L2F];

// ---------------- init ----------------
__global__ void init_kernel() {
    int gid = blockIdx.x * blockDim.x + threadIdx.x;
    if (gid < NTOT) { g_counts[gid] = 0; g_deg[gid] = 1.0f; }
    if (gid < 64)   { g_colsum[gid] = 0.f; g_colsumsq[gid] = 0.f; }
}

// ---------------- column stats (mean/std, ddof=1) ----------------
__global__ void col_stats_kernel(const float* __restrict__ x) {
    __shared__ float ssum[256], ssq[256];
    int c  = threadIdx.x & 63;
    int rr = threadIdx.x >> 6;
    float s = 0.f, q = 0.f;
    for (int row = blockIdx.x * 4 + rr; row < NTOT; row += gridDim.x * 4) {
        float v = x[(size_t)row * 64 + c];
        s += v; q += v * v;
    }
    ssum[threadIdx.x] = s; ssq[threadIdx.x] = q;
    __syncthreads();
    if (threadIdx.x < 64) {
        float S = ssum[threadIdx.x] + ssum[threadIdx.x + 64] + ssum[threadIdx.x + 128] + ssum[threadIdx.x + 192];
        float Q = ssq [threadIdx.x] + ssq [threadIdx.x + 64] + ssq [threadIdx.x + 128] + ssq [threadIdx.x + 192];
        atomicAdd(&g_colsum[threadIdx.x], S);
        atomicAdd(&g_colsumsq[threadIdx.x], Q);
    }
}

__global__ void stats_finalize_kernel() {
    int c = threadIdx.x;
    if (c < 64) {
        float n = (float)NTOT;
        float mean = g_colsum[c] / n;
        float var  = (g_colsumsq[c] - n * mean * mean) / (n - 1.0f);
        g_mean[c] = mean;
        g_rstd[c] = rsqrtf(var);
    }
}

// ---------------- edge pass 1: histogram + weighted degree ----------------
__global__ void edge_pass1_kernel(const int* __restrict__ ei, const float* __restrict__ ea) {
    int e = blockIdx.x * blockDim.x + threadIdx.x;
    if (e >= ETOT) return;
    int dst = ei[ETOT + e];
    float w = fabsf(((const float2*)ea)[e].x);
    atomicAdd(&g_counts[dst], 1);
    atomicAdd(&g_deg[dst], w);
}

// ---------------- scan (exclusive) over counts ----------------
__global__ void scan1_kernel() {
    __shared__ int tmp[1024];
    int gid = blockIdx.x * 1024 + threadIdx.x;
    int v = g_counts[gid];
    tmp[threadIdx.x] = v;
    __syncthreads();
    int val = v;
    for (int off = 1; off < 1024; off <<= 1) {
        int add = (threadIdx.x >= off) ? tmp[threadIdx.x - off] : 0;
        __syncthreads();
        val += add;
        tmp[threadIdx.x] = val;
        __syncthreads();
    }
    g_rowptr[gid] = val - v;           // exclusive, local to block
    if (threadIdx.x == 1023) g_bsums[blockIdx.x] = val;
}

__global__ void scan2_kernel() {
    __shared__ int tmp[128];
    int t = threadIdx.x;
    int v = (t < NTOT / 1024) ? g_bsums[t] : 0;
    tmp[t] = v;
    __syncthreads();
    int val = v;
    for (int off = 1; off < 128; off <<= 1) {
        int add = (t >= off) ? tmp[t - off] : 0;
        __syncthreads();
        val += add;
        tmp[t] = val;
        __syncthreads();
    }
    if (t < NTOT / 1024) g_bsums[t] = val - v;   // exclusive
}

__global__ void scan3_kernel() {
    int gid = blockIdx.x * blockDim.x + threadIdx.x;
    if (gid >= NTOT) return;
    int rp = g_rowptr[gid] + g_bsums[gid >> 10];
    g_rowptr[gid] = rp;
    g_cursor[gid] = rp;
    g_dis[gid] = rsqrtf(g_deg[gid]);   // deg >= 1 always (self loop weight 1)
    if (gid == 0) g_rowptr[NTOT] = ETOT;
}

// ---------------- edge pass 2: scatter into CSR (weights pre-scaled by dis[src]) ----------------
__global__ void edge_scatter_kernel(const int* __restrict__ ei, const float* __restrict__ ea) {
    int e = blockIdx.x * blockDim.x + threadIdx.x;
    if (e >= ETOT) return;
    int dst = ei[ETOT + e];
    int src = ei[e];
    float w = fabsf(((const float2*)ea)[e].x) * g_dis[src];
    int pos = atomicAdd(&g_cursor[dst], 1);
    g_csrsrc[pos] = src;
    g_csrw[pos] = w;
}

// ---------------- split-TF32 MMA GEMM ----------------
// C[M,Nout] = A[M,K] @ B + bias + bias2, fp32-grade accuracy via 2-term tf32 split.
// Block: 128 rows x NT cols, 256 threads (8 warps x 16 rows). Whole K in smem.
__device__ __forceinline__ uint32_t f2tf(float x) {
    uint32_t r;
    asm("cvt.rna.tf32.f32 %0, %1;" : "=r"(r) : "f"(x));
    return r;
}
__device__ __forceinline__ void mma8(float* c,
                                     uint32_t a0, uint32_t a1, uint32_t a2, uint32_t a3,
                                     uint32_t b0, uint32_t b1) {
    asm volatile(
        "mma.sync.aligned.m16n8k8.row.col.f32.tf32.tf32.f32 "
        "{%0,%1,%2,%3},{%4,%5,%6,%7},{%8,%9},{%0,%1,%2,%3};"
        : "+f"(c[0]), "+f"(c[1]), "+f"(c[2]), "+f"(c[3])
        : "r"(a0), "r"(a1), "r"(a2), "r"(a3), "r"(b0), "r"(b1));
}

template<int K, int NT, bool NORM, bool TRANSB>
__global__ __launch_bounds__(256) void mma_gemm_kernel(
        const float* __restrict__ A, const float* __restrict__ Bm,
        const float* __restrict__ bias, const float* __restrict__ bias2,
        float* __restrict__ C, int Nout) {
    constexpr int SA = K + 4;     // (SA mod 32)==4 -> conflict-free A frag loads
    constexpr int SB = NT + 8;    // (SB mod 32)==8 -> conflict-free B frag loads
    constexpr int NF = NT / 8;
    extern __shared__ float smem[];
    float*    As = smem;                               // [128][SA]
    uint32_t* Bh = (uint32_t*)(smem + 128 * SA);       // [K][SB]
    uint32_t* Bl = Bh + K * SB;                        // [K][SB]

    int tid = threadIdx.x;
    int m0 = blockIdx.x * 128;
    int n0 = blockIdx.y * NT;

    // load A tile (optionally normalized)
    constexpr int K4 = K / 4;
    for (int idx = tid; idx < 128 * K4; idx += 256) {
        int r = idx / K4, c4 = (idx - r * K4) * 4;
        float4 a = *(const float4*)(A + (size_t)(m0 + r) * K + c4);
        if (NORM) {
            a.x = (a.x - g_mean[c4])     * g_rstd[c4];
            a.y = (a.y - g_mean[c4 + 1]) * g_rstd[c4 + 1];
            a.z = (a.z - g_mean[c4 + 2]) * g_rstd[c4 + 2];
            a.w = (a.w - g_mean[c4 + 3]) * g_rstd[c4 + 3];
        }
        float* d = As + r * SA + c4;
        d[0] = a.x; d[1] = a.y; d[2] = a.z; d[3] = a.w;
    }
    // load B tile, pre-split into tf32 hi/lo
    for (int idx = tid; idx < K * NT; idx += 256) {
        int k = idx / NT, n = idx - k * NT;
        float v = TRANSB ? Bm[(size_t)(n0 + n) * K + k]
                         : Bm[(size_t)k * Nout + n0 + n];
        uint32_t h = f2tf(v);
        Bh[k * SB + n] = h;
        Bl[k * SB + n] = f2tf(v - __uint_as_float(h));
    }
    __syncthreads();

    int lane = tid & 31, warp = tid >> 5;
    int gid = lane >> 2, tig = lane & 3;
    int wm = warp * 16;

    float c[NF][4];
    #pragma unroll
    for (int f = 0; f < NF; f++) { c[f][0] = 0.f; c[f][1] = 0.f; c[f][2] = 0.f; c[f][3] = 0.f; }

    for (int k0 = 0; k0 < K; k0 += 8) {
        const float* Ar = As + (wm + gid) * SA + k0 + tig;
        float a0f = Ar[0];
        float a1f = Ar[8 * SA];
        float a2f = Ar[4];
        float a3f = Ar[8 * SA + 4];
        uint32_t ah0 = f2tf(a0f), ah1 = f2tf(a1f), ah2 = f2tf(a2f), ah3 = f2tf(a3f);
        uint32_t al0 = f2tf(a0f - __uint_as_float(ah0));
        uint32_t al1 = f2tf(a1f - __uint_as_float(ah1));
        uint32_t al2 = f2tf(a2f - __uint_as_float(ah2));
        uint32_t al3 = f2tf(a3f - __uint_as_float(ah3));
        int boff = (k0 + tig) * SB + gid;
        #pragma unroll
        for (int nf = 0; nf < NF; nf++) {
            uint32_t b0h = Bh[boff + nf * 8];
            uint32_t b1h = Bh[boff + nf * 8 + 4 * SB];
            uint32_t b0l = Bl[boff + nf * 8];
            uint32_t b1l = Bl[boff + nf * 8 + 4 * SB];
            mma8(c[nf], ah0, ah1, ah2, ah3, b0h, b1h);
            mma8(c[nf], al0, al1, al2, al3, b0h, b1h);
            mma8(c[nf], ah0, ah1, ah2, ah3, b0l, b1l);
        }
    }

    // epilogue
    int r0 = m0 + wm + gid;
    #pragma unroll
    for (int nf = 0; nf < NF; nf++) {
        int n = n0 + nf * 8 + tig * 2;
        float bx = 0.f, by = 0.f;
        if (bias)  { bx += bias[n];  by += bias[n + 1]; }
        if (bias2) { bx += bias2[n]; by += bias2[n + 1]; }
        *(float2*)(C + (size_t)r0 * Nout + n)       = make_float2(c[nf][0] + bx, c[nf][1] + by);
        *(float2*)(C + (size_t)(r0 + 8) * Nout + n) = make_float2(c[nf][2] + bx, c[nf][3] + by);
    }
}

// ---------------- GCN aggregation: one warp per destination node, 4-edge unroll ----------------
template<int F>
__global__ void agg_kernel(const float* __restrict__ hpre, const float* __restrict__ bias,
                           float* __restrict__ out) {
    int warpId = (blockIdx.x * blockDim.x + threadIdx.x) >> 5;
    int lane = threadIdx.x & 31;
    if (warpId >= NTOT) return;
    const int R = F / 32;
    int i = warpId;
    int beg = g_rowptr[i], end = g_rowptr[i + 1];
    float di = g_dis[i];
    float acc[R];
    #pragma unroll
    for (int r = 0; r < R; r++) acc[r] = 0.f;

    for (int e0 = beg; e0 < end; e0 += 32) {
        int cnt = min(32, end - e0);
        int s_l = i; float w_l = 0.f;               // safe defaults: weight 0
        if (lane < cnt) {
            s_l = g_csrsrc[e0 + lane];
            w_l = g_csrw[e0 + lane];                // pre-scaled by dis[src]
        }
        for (int j = 0; j < cnt; j += 4) {
            int   s0 = __shfl_sync(0xffffffffu, s_l, j);
            int   s1 = __shfl_sync(0xffffffffu, s_l, j + 1);
            int   s2 = __shfl_sync(0xffffffffu, s_l, j + 2);
            int   s3 = __shfl_sync(0xffffffffu, s_l, j + 3);
            float w0 = __shfl_sync(0xffffffffu, w_l, j);
            float w1 = __shfl_sync(0xffffffffu, w_l, j + 1);
            float w2 = __shfl_sync(0xffffffffu, w_l, j + 2);
            float w3 = __shfl_sync(0xffffffffu, w_l, j + 3);
            const float* r0 = hpre + (size_t)s0 * F + lane;
            const float* r1 = hpre + (size_t)s1 * F + lane;
            const float* r2 = hpre + (size_t)s2 * F + lane;
            const float* r3 = hpre + (size_t)s3 * F + lane;
            float v0[R], v1[R], v2[R], v3[R];
            #pragma unroll
            for (int r = 0; r < R; r++) { v0[r] = r0[32 * r]; v1[r] = r1[32 * r]; v2[r] = r2[32 * r]; v3[r] = r3[32 * r]; }
            #pragma unroll
            for (int r = 0; r < R; r++)
                acc[r] += v0[r] * w0 + v1[r] * w1 + v2[r] * w2 + v3[r] * w3;
        }
    }
    const float* self = hpre + (size_t)i * F;
    #pragma unroll
    for (int r = 0; r < R; r++) {
        float v = acc[r] * di + self[lane + 32 * r] * di * di + bias[lane + 32 * r];
        out[(size_t)i * F + lane + 32 * r] = fmaxf(v, 0.f);
    }
}

// ---------------- LSTM: register-resident weights ----------------
__device__ __forceinline__ float sigm(float x) { return 1.0f / (1.0f + expf(-x)); }

__global__ __launch_bounds__(256) void lstm_kernel(const float* __restrict__ xg,
                                                   const float* __restrict__ w_hh,
                                                   float* __restrict__ hfinal) {
    __shared__ float  h_sm[2][64];
    __shared__ __align__(16) float4 p_sm[2][4][64];
    int t = threadIdx.x;
    int j = t & 63, kc = t >> 6;
    int k0 = kc * 16;

    float wI[16], wF[16], wG[16], wO[16];
    #pragma unroll
    for (int kk = 0; kk < 16; kk++) {
        wI[kk] = w_hh[(size_t)(      j) * 64 + k0 + kk];
        wF[kk] = w_hh[(size_t)( 64 + j) * 64 + k0 + kk];
        wG[kk] = w_hh[(size_t)(128 + j) * 64 + k0 + kk];
        wO[kk] = w_hh[(size_t)(192 + j) * 64 + k0 + kk];
    }
    int seq0 = blockIdx.x * 2;
    int bA = seq0 / NODES,       nA = seq0 % NODES;
    int bB = (seq0 + 1) / NODES, nB = (seq0 + 1) % NODES;

    float c_state = 0.f;          // valid on threads t<128 (reducer for seq kc, unit j)
    if (t < 128) h_sm[kc][j] = 0.f;
    __syncthreads();

    for (int step = 0; step < TSTEPS; step++) {
        float ai = 0.f, af = 0.f, ag = 0.f, ao = 0.f;   // seq0 partials
        float bi = 0.f, bf = 0.f, bg = 0.f, bo = 0.f;   // seq1 partials
        #pragma unroll
        for (int kk = 0; kk < 16; kk++) {
            float h0 = h_sm[0][k0 + kk];
            float h1 = h_sm[1][k0 + kk];
            ai += h0 * wI[kk]; af += h0 * wF[kk]; ag += h0 * wG[kk]; ao += h0 * wO[kk];
            bi += h1 * wI[kk]; bf += h1 * wF[kk]; bg += h1 * wG[kk]; bo += h1 * wO[kk];
        }
        p_sm[0][kc][j] = make_float4(ai, af, ag, ao);
        p_sm[1][kc][j] = make_float4(bi, bf, bg, bo);
        __syncthreads();
        if (t < 128) {
            int s = kc;                                  // 0 or 1
            int bb = s ? bB : bA, nn = s ? nB : nA;
            size_t row = ((size_t)(bb * TSTEPS + step) * NODES + nn) * GATES;
            float4 p = p_sm[s][0][j];
            float4 q = p_sm[s][1][j];
            float4 r = p_sm[s][2][j];
            float4 w = p_sm[s][3][j];
            float gi = p.x + q.x + r.x + w.x + xg[row + j];
            float gf = p.y + q.y + r.y + w.y + xg[row + 64 + j];
            float gg = p.z + q.z + r.z + w.z + xg[row + 128 + j];
            float go = p.w + q.w + r.w + w.w + xg[row + 192 + j];
            c_state = sigm(gf) * c_state + sigm(gi) * tanhf(gg);
            h_sm[s][j] = sigm(go) * tanhf(c_state);
        }
        __syncthreads();
    }
    if (t < 128) hfinal[(size_t)(seq0 + kc) * 64 + j] = h_sm[kc][j];
}

// ---------------- head: fc1 + relu + fc2 + softmax ----------------
__global__ void head_kernel(const float* __restrict__ hfinal,
                            const float* __restrict__ fc1_w, const float* __restrict__ fc1_b,
                            const float* __restrict__ fc2_w, const float* __restrict__ fc2_b,
                            float* __restrict__ out) {
    __shared__ float h[64];
    __shared__ float f1[128];
    __shared__ float logits[3];
    int s = blockIdx.x, tid = threadIdx.x;
    if (tid < 64) h[tid] = hfinal[(size_t)s * 64 + tid];
    __syncthreads();
    float acc = fc1_b[tid];
    #pragma unroll 8
    for (int k = 0; k < 64; k++) acc += h[k] * fc1_w[(size_t)tid * 64 + k];
    f1[tid] = fmaxf(acc, 0.f);
    __syncthreads();
    if (tid < 3) {
        float l = fc2_b[tid];
        #pragma unroll 8
        for (int k = 0; k < 128; k++) l += f1[k] * fc2_w[(size_t)tid * 128 + k];
        logits[tid] = l;
    }
    __syncthreads();
    if (tid == 0) {
        float m = fmaxf(logits[0], fmaxf(logits[1], logits[2]));
        float e0 = expf(logits[0] - m), e1 = expf(logits[1] - m), e2 = expf(logits[2] - m);
        float inv = 1.0f / (e0 + e1 + e2);
        out[(size_t)s * 3 + 0] = e0 * inv;
        out[(size_t)s * 3 + 1] = e1 * inv;
        out[(size_t)s * 3 + 2] = e2 * inv;
    }
}

// ---------------- host launcher ----------------
static void* sym_addr(const void* sym) {
    void* p = nullptr;
    cudaGetSymbolAddress(&p, sym);
    return p;
}

extern "C" void kernel_launch(void* const* d_in, const int* in_sizes, int n_in,
                              void* d_out, int out_size) {
    const float* x        = (const float*)d_in[0];
    const float* ea       = (const float*)d_in[1];
    const float* conv1_w  = (const float*)d_in[2];
    const float* conv1_b  = (const float*)d_in[3];
    const float* conv2_w  = (const float*)d_in[4];
    const float* conv2_b  = (const float*)d_in[5];
    const float* w_ih     = (const float*)d_in[6];
    const float* w_hh     = (const float*)d_in[7];
    const float* b_ih     = (const float*)d_in[8];
    const float* b_hh     = (const float*)d_in[9];
    const float* fc1_w    = (const float*)d_in[10];
    const float* fc1_b    = (const float*)d_in[11];
    const float* fc2_w    = (const float*)d_in[12];
    const float* fc2_b    = (const float*)d_in[13];
    const int*   ei       = (const int*)d_in[14];
    float* out = (float*)d_out;

    float* h1pre = (float*)sym_addr(g_h1pre);
    float* h1    = (float*)sym_addr(g_h1);
    float* h2pre = (float*)sym_addr(g_h2pre);
    float* h2    = (float*)sym_addr(g_h2);
    float* xg    = (float*)sym_addr(g_xg);
    float* hfin  = (float*)sym_addr(g_hfin);

    // dynamic smem sizes per GEMM instantiation
    auto g1 = mma_gemm_kernel<64, 96, true,  false>;
    auto g2 = mma_gemm_kernel<96, 64, false, false>;
    auto g3 = mma_gemm_kernel<64, 128, false, true>;
    size_t s1 = (size_t)(128 * 68  + 2 * 64 * 104) * 4;   //  88.1 KB
    size_t s2 = (size_t)(128 * 100 + 2 * 96 * 72 ) * 4;   // 106.5 KB
    size_t s3 = (size_t)(128 * 68  + 2 * 64 * 136) * 4;   // 104.4 KB
    cudaFuncSetAttribute(g1, cudaFuncAttributeMaxDynamicSharedMemorySize, (int)s1);
    cudaFuncSetAttribute(g2, cudaFuncAttributeMaxDynamicSharedMemorySize, (int)s2);
    cudaFuncSetAttribute(g3, cudaFuncAttributeMaxDynamicSharedMemorySize, (int)s3);

    // stats + graph structure
    init_kernel<<<(NTOT + 255) / 256, 256>>>();
    col_stats_kernel<<<200, 256>>>(x);
    stats_finalize_kernel<<<1, 64>>>();
    edge_pass1_kernel<<<ETOT / 256, 256>>>(ei, ea);
    scan1_kernel<<<NTOT / 1024, 1024>>>();
    scan2_kernel<<<1, 128>>>();
    scan3_kernel<<<(NTOT + 255) / 256, 256>>>();
    edge_scatter_kernel<<<ETOT / 256, 256>>>(ei, ea);

    // conv1: h1 = relu(agg(norm(x) @ W1) + b1)
    g1<<<dim3(NTOT / 128, 1), 256, s1>>>(x, conv1_w, nullptr, nullptr, h1pre, L1F);
    agg_kernel<L1F><<<NTOT / 8, 256>>>(h1pre, conv1_b, h1);

    // conv2: h2 = relu(agg(h1 @ W2) + b2)
    g2<<<dim3(NTOT / 128, 1), 256, s2>>>(h1, conv2_w, nullptr, nullptr, h2pre, L2F);
    agg_kernel<L2F><<<NTOT / 8, 256>>>(h2pre, conv2_b, h2);

    // LSTM input projection: xg = h2 @ w_ih^T + (b_ih + b_hh)
    g3<<<dim3(NTOT / 128, 2), 256, s3>>>(h2, w_ih, b_ih, b_hh, xg, GATES);

    // recurrence (register-resident weights, 2 seqs/block)
    lstm_kernel<<<NSEQ / 2, 256>>>(xg, w_hh, hfin);

    // head
    head_kernel<<<NSEQ, 128>>>(hfin, fc1_w, fc1_b, fc2_w, fc2_b, out);
}

// round 6
// speedup vs baseline: 1.4896x; 1.4896x over previous
#include <cuda_runtime.h>
#include <math.h>

// ---------------- problem constants ----------------
#define NTOT   102400          // B*T*NODES
#define ETOT   1638400         // edges
#define BATCH  8
#define TSTEPS 32
#define NODES  400
#define NSEQ   (BATCH*NODES)   // 3200
#define D_IN   64
#define L1F    96
#define L2F    64
#define GATES  256             // 4*64
#define FC1F   128
#define FC2F   3

// ---------------- device scratch (static: allowed) ----------------
__device__ float g_colsum[64];
__device__ float g_colsumsq[64];
__device__ float g_mean[64];
__device__ float g_rstd[64];
__device__ int   g_counts[NTOT];
__device__ int   g_rowptr[NTOT + 1];
__device__ int   g_cursor[NTOT];
__device__ int   g_bsums[128];
__device__ float g_deg[NTOT];
__device__ float g_dis[NTOT];
__device__ int   g_csrsrc[ETOT];
__device__ float g_csrw[ETOT];
__device__ __align__(16) float g_aggx [(size_t)NTOT * D_IN];
__device__ float g_h1   [(size_t)NTOT * L1F];
__device__ __align__(16) float g_h2pre[(size_t)NTOT * L2F];
__device__ float g_h2   [(size_t)NTOT * L2F];
__device__ float g_xg   [(size_t)NTOT * GATES];
__device__ float g_hfin [(size_t)NSEQ * L2F];

// ---------------- init ----------------
__global__ void init_kernel() {
    int gid = blockIdx.x * blockDim.x + threadIdx.x;
    if (gid < NTOT) { g_counts[gid] = 0; g_deg[gid] = 1.0f; }
    if (gid < 64)   { g_colsum[gid] = 0.f; g_colsumsq[gid] = 0.f; }
}

// ---------------- column stats (mean/std, ddof=1) ----------------
__global__ void col_stats_kernel(const float* __restrict__ x) {
    __shared__ float ssum[256], ssq[256];
    int c  = threadIdx.x & 63;
    int rr = threadIdx.x >> 6;
    float s = 0.f, q = 0.f;
    for (int row = blockIdx.x * 4 + rr; row < NTOT; row += gridDim.x * 4) {
        float v = x[(size_t)row * 64 + c];
        s += v; q += v * v;
    }
    ssum[threadIdx.x] = s; ssq[threadIdx.x] = q;
    __syncthreads();
    if (threadIdx.x < 64) {
        float S = ssum[threadIdx.x] + ssum[threadIdx.x + 64] + ssum[threadIdx.x + 128] + ssum[threadIdx.x + 192];
        float Q = ssq [threadIdx.x] + ssq [threadIdx.x + 64] + ssq [threadIdx.x + 128] + ssq [threadIdx.x + 192];
        atomicAdd(&g_colsum[threadIdx.x], S);
        atomicAdd(&g_colsumsq[threadIdx.x], Q);
    }
}

__global__ void stats_finalize_kernel() {
    int c = threadIdx.x;
    if (c < 64) {
        float n = (float)NTOT;
        float mean = g_colsum[c] / n;
        float var  = (g_colsumsq[c] - n * mean * mean) / (n - 1.0f);
        g_mean[c] = mean;
        g_rstd[c] = rsqrtf(var);
    }
}

// ---------------- edge pass 1: histogram + weighted degree ----------------
__global__ void edge_pass1_kernel(const int* __restrict__ ei, const float* __restrict__ ea) {
    int e = blockIdx.x * blockDim.x + threadIdx.x;
    if (e >= ETOT) return;
    int dst = ei[ETOT + e];
    float w = fabsf(((const float2*)ea)[e].x);
    atomicAdd(&g_counts[dst], 1);
    atomicAdd(&g_deg[dst], w);
}

// ---------------- scan (exclusive) over counts ----------------
__global__ void scan1_kernel() {
    __shared__ int tmp[1024];
    int gid = blockIdx.x * 1024 + threadIdx.x;
    int v = g_counts[gid];
    tmp[threadIdx.x] = v;
    __syncthreads();
    int val = v;
    for (int off = 1; off < 1024; off <<= 1) {
        int add = (threadIdx.x >= off) ? tmp[threadIdx.x - off] : 0;
        __syncthreads();
        val += add;
        tmp[threadIdx.x] = val;
        __syncthreads();
    }
    g_rowptr[gid] = val - v;           // exclusive, local to block
    if (threadIdx.x == 1023) g_bsums[blockIdx.x] = val;
}

__global__ void scan2_kernel() {
    __shared__ int tmp[128];
    int t = threadIdx.x;
    int v = (t < NTOT / 1024) ? g_bsums[t] : 0;
    tmp[t] = v;
    __syncthreads();
    int val = v;
    for (int off = 1; off < 128; off <<= 1) {
        int add = (t >= off) ? tmp[t - off] : 0;
        __syncthreads();
        val += add;
        tmp[t] = val;
        __syncthreads();
    }
    if (t < NTOT / 1024) g_bsums[t] = val - v;   // exclusive
}

__global__ void scan3_kernel() {
    int gid = blockIdx.x * blockDim.x + threadIdx.x;
    if (gid >= NTOT) return;
    int rp = g_rowptr[gid] + g_bsums[gid >> 10];
    g_rowptr[gid] = rp;
    g_cursor[gid] = rp;
    g_dis[gid] = rsqrtf(g_deg[gid]);   // deg >= 1 always (self loop weight 1)
    if (gid == 0) g_rowptr[NTOT] = ETOT;
}

// ---------------- edge pass 2: scatter into CSR (weights pre-scaled by dis[src]) ----------------
__global__ void edge_scatter_kernel(const int* __restrict__ ei, const float* __restrict__ ea) {
    int e = blockIdx.x * blockDim.x + threadIdx.x;
    if (e >= ETOT) return;
    int dst = ei[ETOT + e];
    int src = ei[e];
    float w = fabsf(((const float2*)ea)[e].x) * g_dis[src];
    int pos = atomicAdd(&g_cursor[dst], 1);
    g_csrsrc[pos] = src;
    g_csrw[pos] = w;
}

// ---------------- tiled SGEMM: C[M,Nout] = A[M,K] * B + bias (+bias2) [+relu] ----------------
// BM=64, BN=64, BK=16, 256 threads, thread tile 4x4, float4 smem paths
template<bool TRANSB, bool RELU>
__global__ void gemm_kernel(const float* __restrict__ A, const float* __restrict__ Bm,
                            const float* __restrict__ bias, const float* __restrict__ bias2,
                            float* __restrict__ C, int K, int Nout) {
    __shared__ __align__(16) float As[16][68];
    __shared__ __align__(16) float Bs[16][68];
    int tid = threadIdx.x;
    int tx = tid & 15, ty = tid >> 4;
    int m0 = blockIdx.x * 64, n0 = blockIdx.y * 64;
    float acc[4][4] = {};
    for (int k0 = 0; k0 < K; k0 += 16) {
        // A tile: 64 rows x 16 cols, one float4 per thread
        {
            int r = tid >> 2, c4 = (tid & 3) * 4;
            float4 a = *(const float4*)(A + (size_t)(m0 + r) * K + k0 + c4);
            As[c4][r] = a.x; As[c4 + 1][r] = a.y; As[c4 + 2][r] = a.z; As[c4 + 3][r] = a.w;
        }
        // B tile: 16 rows (k) x 64 cols (n)
        if (!TRANSB) {
            int r = tid >> 4, c = (tid & 15) * 4;
            int n = n0 + c, kk = k0 + r;
            float4 b = make_float4(0.f, 0.f, 0.f, 0.f);
            if (n + 3 < Nout) {
                b = *(const float4*)(Bm + (size_t)kk * Nout + n);
            } else {
                if (n     < Nout) b.x = Bm[(size_t)kk * Nout + n];
                if (n + 1 < Nout) b.y = Bm[(size_t)kk * Nout + n + 1];
                if (n + 2 < Nout) b.z = Bm[(size_t)kk * Nout + n + 2];
                if (n + 3 < Nout) b.w = Bm[(size_t)kk * Nout + n + 3];
            }
            Bs[r][c] = b.x; Bs[r][c + 1] = b.y; Bs[r][c + 2] = b.z; Bs[r][c + 3] = b.w;
        } else {
            int c = tid & 63, r4 = (tid >> 6) * 4;      // n0+c always < Nout on TRANSB path
            float4 b = *(const float4*)(Bm + (size_t)(n0 + c) * K + k0 + r4);
            Bs[r4][c] = b.x; Bs[r4 + 1][c] = b.y; Bs[r4 + 2][c] = b.z; Bs[r4 + 3][c] = b.w;
        }
        __syncthreads();
        #pragma unroll
        for (int kk = 0; kk < 16; kk++) {
            float4 a = *(const float4*)&As[kk][ty * 4];
            float4 b = *(const float4*)&Bs[kk][tx * 4];
            acc[0][0] += a.x * b.x; acc[0][1] += a.x * b.y; acc[0][2] += a.x * b.z; acc[0][3] += a.x * b.w;
            acc[1][0] += a.y * b.x; acc[1][1] += a.y * b.y; acc[1][2] += a.y * b.z; acc[1][3] += a.y * b.w;
            acc[2][0] += a.z * b.x; acc[2][1] += a.z * b.y; acc[2][2] += a.z * b.z; acc[2][3] += a.z * b.w;
            acc[3][0] += a.w * b.x; acc[3][1] += a.w * b.y; acc[3][2] += a.w * b.z; acc[3][3] += a.w * b.w;
        }
        __syncthreads();
    }
    #pragma unroll
    for (int i = 0; i < 4; i++) {
        int m = m0 + ty * 4 + i;
        int n = n0 + tx * 4;
        float4 v;
        v.x = acc[i][0]; v.y = acc[i][1]; v.z = acc[i][2]; v.w = acc[i][3];
        if (bias)  { v.x += bias[n];  v.y += bias[n + 1];  v.z += bias[n + 2];  v.w += bias[n + 3]; }
        if (bias2) { v.x += bias2[n]; v.y += bias2[n + 1]; v.z += bias2[n + 2]; v.w += bias2[n + 3]; }
        if (RELU)  { v.x = fmaxf(v.x, 0.f); v.y = fmaxf(v.y, 0.f); v.z = fmaxf(v.z, 0.f); v.w = fmaxf(v.w, 0.f); }
        if (n + 3 < Nout) {
            *(float4*)(C + (size_t)m * Nout + n) = v;
        } else {
            if (n     < Nout) C[(size_t)m * Nout + n]     = v.x;
            if (n + 1 < Nout) C[(size_t)m * Nout + n + 1] = v.y;
            if (n + 2 < Nout) C[(size_t)m * Nout + n + 2] = v.z;
            if (n + 3 < Nout) C[(size_t)m * Nout + n + 3] = v.w;
        }
    }
}

// ---------------- conv1 aggregation over RAW x, normalization folded into epilogue ----------------
// aggx_i[c] = r[c]*( di*S[c] + di^2*x_i[c] - (di*W + di^2)*m[c] ),  S=sum wd_j*x_j, W=sum wd_j
__global__ void agg_x_kernel(const float* __restrict__ x, float* __restrict__ out) {
    int warpId = (blockIdx.x * blockDim.x + threadIdx.x) >> 5;
    int lane = threadIdx.x & 31;
    if (warpId >= NTOT) return;
    int i = warpId;
    int beg = g_rowptr[i], end = g_rowptr[i + 1];
    float di = g_dis[i];
    float acc0 = 0.f, acc1 = 0.f, wsum = 0.f;

    for (int e0 = beg; e0 < end; e0 += 32) {
        int cnt = min(32, end - e0);
        int s_l = i; float w_l = 0.f;               // padding lanes: weight 0
        if (lane < cnt) {
            s_l = g_csrsrc[e0 + lane];
            w_l = g_csrw[e0 + lane];                // pre-scaled by dis[src]
        }
        for (int j = 0; j < cnt; j += 4) {
            int   s0 = __shfl_sync(0xffffffffu, s_l, j);
            int   s1 = __shfl_sync(0xffffffffu, s_l, j + 1);
            int   s2 = __shfl_sync(0xffffffffu, s_l, j + 2);
            int   s3 = __shfl_sync(0xffffffffu, s_l, j + 3);
            float w0 = __shfl_sync(0xffffffffu, w_l, j);
            float w1 = __shfl_sync(0xffffffffu, w_l, j + 1);
            float w2 = __shfl_sync(0xffffffffu, w_l, j + 2);
            float w3 = __shfl_sync(0xffffffffu, w_l, j + 3);
            const float* r0 = x + (size_t)s0 * 64 + lane;
            const float* r1 = x + (size_t)s1 * 64 + lane;
            const float* r2 = x + (size_t)s2 * 64 + lane;
            const float* r3 = x + (size_t)s3 * 64 + lane;
            float a0 = r0[0],  a1 = r1[0],  a2 = r2[0],  a3 = r3[0];
            float b0 = r0[32], b1 = r1[32], b2 = r2[32], b3 = r3[32];
            acc0 += a0 * w0 + a1 * w1 + a2 * w2 + a3 * w3;
            acc1 += b0 * w0 + b1 * w1 + b2 * w2 + b3 * w3;
            wsum += w0 + w1 + w2 + w3;
        }
    }
    float di2 = di * di;
    float coef = di * wsum + di2;
    float xi0 = x[(size_t)i * 64 + lane];
    float xi1 = x[(size_t)i * 64 + lane + 32];
    out[(size_t)i * 64 + lane]      = g_rstd[lane]      * (di * acc0 + di2 * xi0 - coef * g_mean[lane]);
    out[(size_t)i * 64 + lane + 32] = g_rstd[lane + 32] * (di * acc1 + di2 * xi1 - coef * g_mean[lane + 32]);
}

// ---------------- GCN aggregation (conv2): one warp per dst node, bias+relu epilogue ----------------
template<int F>
__global__ void agg_kernel(const float* __restrict__ hpre, const float* __restrict__ bias,
                           float* __restrict__ out) {
    int warpId = (blockIdx.x * blockDim.x + threadIdx.x) >> 5;
    int lane = threadIdx.x & 31;
    if (warpId >= NTOT) return;
    const int R = F / 32;
    int i = warpId;
    int beg = g_rowptr[i], end = g_rowptr[i + 1];
    float di = g_dis[i];
    float acc[R];
    #pragma unroll
    for (int r = 0; r < R; r++) acc[r] = 0.f;

    for (int e0 = beg; e0 < end; e0 += 32) {
        int cnt = min(32, end - e0);
        int s_l = i; float w_l = 0.f;
        if (lane < cnt) {
            s_l = g_csrsrc[e0 + lane];
            w_l = g_csrw[e0 + lane];                // pre-scaled by dis[src]
        }
        for (int j = 0; j < cnt; j += 4) {
            int   s0 = __shfl_sync(0xffffffffu, s_l, j);
            int   s1 = __shfl_sync(0xffffffffu, s_l, j + 1);
            int   s2 = __shfl_sync(0xffffffffu, s_l, j + 2);
            int   s3 = __shfl_sync(0xffffffffu, s_l, j + 3);
            float w0 = __shfl_sync(0xffffffffu, w_l, j);
            float w1 = __shfl_sync(0xffffffffu, w_l, j + 1);
            float w2 = __shfl_sync(0xffffffffu, w_l, j + 2);
            float w3 = __shfl_sync(0xffffffffu, w_l, j + 3);
            const float* r0 = hpre + (size_t)s0 * F + lane;
            const float* r1 = hpre + (size_t)s1 * F + lane;
            const float* r2 = hpre + (size_t)s2 * F + lane;
            const float* r3 = hpre + (size_t)s3 * F + lane;
            float v0[R], v1[R], v2[R], v3[R];
            #pragma unroll
            for (int r = 0; r < R; r++) { v0[r] = r0[32 * r]; v1[r] = r1[32 * r]; v2[r] = r2[32 * r]; v3[r] = r3[32 * r]; }
            #pragma unroll
            for (int r = 0; r < R; r++)
                acc[r] += v0[r] * w0 + v1[r] * w1 + v2[r] * w2 + v3[r] * w3;
        }
    }
    const float* self = hpre + (size_t)i * F;
    #pragma unroll
    for (int r = 0; r < R; r++) {
        float v = acc[r] * di + self[lane + 32 * r] * di * di + bias[lane + 32 * r];
        out[(size_t)i * F + lane + 32 * r] = fmaxf(v, 0.f);
    }
}

// ---------------- LSTM: register-resident weights ----------------
__device__ __forceinline__ float sigm(float x) { return 1.0f / (1.0f + expf(-x)); }

__global__ __launch_bounds__(256) void lstm_kernel(const float* __restrict__ xg,
                                                   const float* __restrict__ w_hh,
                                                   float* __restrict__ hfinal) {
    __shared__ float  h_sm[2][64];
    __shared__ __align__(16) float4 p_sm[2][4][64];
    int t = threadIdx.x;
    int j = t & 63, kc = t >> 6;
    int k0 = kc * 16;

    float wI[16], wF[16], wG[16], wO[16];
    #pragma unroll
    for (int kk = 0; kk < 16; kk++) {
        wI[kk] = w_hh[(size_t)(      j) * 64 + k0 + kk];
        wF[kk] = w_hh[(size_t)( 64 + j) * 64 + k0 + kk];
        wG[kk] = w_hh[(size_t)(128 + j) * 64 + k0 + kk];
        wO[kk] = w_hh[(size_t)(192 + j) * 64 + k0 + kk];
    }
    int seq0 = blockIdx.x * 2;
    int bA = seq0 / NODES,       nA = seq0 % NODES;
    int bB = (seq0 + 1) / NODES, nB = (seq0 + 1) % NODES;

    float c_state = 0.f;
    if (t < 128) h_sm[kc][j] = 0.f;
    __syncthreads();

    for (int step = 0; step < TSTEPS; step++) {
        float ai = 0.f, af = 0.f, ag = 0.f, ao = 0.f;
        float bi = 0.f, bf = 0.f, bg = 0.f, bo = 0.f;
        #pragma unroll
        for (int kk = 0; kk < 16; kk++) {
            float h0 = h_sm[0][k0 + kk];
            float h1 = h_sm[1][k0 + kk];
            ai += h0 * wI[kk]; af += h0 * wF[kk]; ag += h0 * wG[kk]; ao += h0 * wO[kk];
            bi += h1 * wI[kk]; bf += h1 * wF[kk]; bg += h1 * wG[kk]; bo += h1 * wO[kk];
        }
        p_sm[0][kc][j] = make_float4(ai, af, ag, ao);
        p_sm[1][kc][j] = make_float4(bi, bf, bg, bo);
        __syncthreads();
        if (t < 128) {
            int s = kc;
            int bb = s ? bB : bA, nn = s ? nB : nA;
            size_t row = ((size_t)(bb * TSTEPS + step) * NODES + nn) * GATES;
            float4 p = p_sm[s][0][j];
            float4 q = p_sm[s][1][j];
            float4 r = p_sm[s][2][j];
            float4 w = p_sm[s][3][j];
            float gi = p.x + q.x + r.x + w.x + xg[row + j];
            float gf = p.y + q.y + r.y + w.y + xg[row + 64 + j];
            float gg = p.z + q.z + r.z + w.z + xg[row + 128 + j];
            float go = p.w + q.w + r.w + w.w + xg[row + 192 + j];
            c_state = sigm(gf) * c_state + sigm(gi) * tanhf(gg);
            h_sm[s][j] = sigm(go) * tanhf(c_state);
        }
        __syncthreads();
    }
    if (t < 128) hfinal[(size_t)(seq0 + kc) * 64 + j] = h_sm[kc][j];
}

// ---------------- head: fc1 + relu + fc2 + softmax ----------------
__global__ void head_kernel(const float* __restrict__ hfinal,
                            const float* __restrict__ fc1_w, const float* __restrict__ fc1_b,
                            const float* __restrict__ fc2_w, const float* __restrict__ fc2_b,
                            float* __restrict__ out) {
    __shared__ float h[64];
    __shared__ float f1[128];
    __shared__ float logits[3];
    int s = blockIdx.x, tid = threadIdx.x;
    if (tid < 64) h[tid] = hfinal[(size_t)s * 64 + tid];
    __syncthreads();
    float acc = fc1_b[tid];
    #pragma unroll 8
    for (int k = 0; k < 64; k++) acc += h[k] * fc1_w[(size_t)tid * 64 + k];
    f1[tid] = fmaxf(acc, 0.f);
    __syncthreads();
    if (tid < 3) {
        float l = fc2_b[tid];
        #pragma unroll 8
        for (int k = 0; k < 128; k++) l += f1[k] * fc2_w[(size_t)tid * 128 + k];
        logits[tid] = l;
    }
    __syncthreads();
    if (tid == 0) {
        float m = fmaxf(logits[0], fmaxf(logits[1], logits[2]));
        float e0 = expf(logits[0] - m), e1 = expf(logits[1] - m), e2 = expf(logits[2] - m);
        float inv = 1.0f / (e0 + e1 + e2);
        out[(size_t)s * 3 + 0] = e0 * inv;
        out[(size_t)s * 3 + 1] = e1 * inv;
        out[(size_t)s * 3 + 2] = e2 * inv;
    }
}

// ---------------- host launcher ----------------
static void* sym_addr(const void* sym) {
    void* p = nullptr;
    cudaGetSymbolAddress(&p, sym);
    return p;
}

extern "C" void kernel_launch(void* const* d_in, const int* in_sizes, int n_in,
                              void* d_out, int out_size) {
    const float* x        = (const float*)d_in[0];
    const float* ea       = (const float*)d_in[1];
    const float* conv1_w  = (const float*)d_in[2];
    const float* conv1_b  = (const float*)d_in[3];
    const float* conv2_w  = (const float*)d_in[4];
    const float* conv2_b  = (const float*)d_in[5];
    const float* w_ih     = (const float*)d_in[6];
    const float* w_hh     = (const float*)d_in[7];
    const float* b_ih     = (const float*)d_in[8];
    const float* b_hh     = (const float*)d_in[9];
    const float* fc1_w    = (const float*)d_in[10];
    const float* fc1_b    = (const float*)d_in[11];
    const float* fc2_w    = (const float*)d_in[12];
    const float* fc2_b    = (const float*)d_in[13];
    const int*   ei       = (const int*)d_in[14];
    float* out = (float*)d_out;

    float* aggx  = (float*)sym_addr(g_aggx);
    float* h1    = (float*)sym_addr(g_h1);
    float* h2pre = (float*)sym_addr(g_h2pre);
    float* h2    = (float*)sym_addr(g_h2);
    float* xg    = (float*)sym_addr(g_xg);
    float* hfin  = (float*)sym_addr(g_hfin);

    // stats + graph structure
    init_kernel<<<(NTOT + 255) / 256, 256>>>();
    col_stats_kernel<<<200, 256>>>(x);
    stats_finalize_kernel<<<1, 64>>>();
    edge_pass1_kernel<<<ETOT / 256, 256>>>(ei, ea);
    scan1_kernel<<<NTOT / 1024, 1024>>>();
    scan2_kernel<<<1, 128>>>();
    scan3_kernel<<<(NTOT + 255) / 256, 256>>>();
    edge_scatter_kernel<<<ETOT / 256, 256>>>(ei, ea);

    // conv1 (reordered): aggx = agg(norm(x));  h1 = relu(aggx @ W1 + b1)
    agg_x_kernel<<<NTOT / 8, 256>>>(x, aggx);
    gemm_kernel<false, true><<<dim3(NTOT / 64, 2), 256>>>(aggx, conv1_w, conv1_b, nullptr, h1, 64, L1F);

    // conv2: h2 = relu(agg(h1 @ W2) + b2)
    gemm_kernel<false, false><<<dim3(NTOT / 64, 1), 256>>>(h1, conv2_w, nullptr, nullptr, h2pre, 96, L2F);
    agg_kernel<L2F><<<NTOT / 8, 256>>>(h2pre, conv2_b, h2);

    // LSTM input projection: xg = h2 @ w_ih^T + (b_ih + b_hh)
    gemm_kernel<true, false><<<dim3(NTOT / 64, 4), 256>>>(h2, w_ih, b_ih, b_hh, xg, 64, GATES);

    // recurrence (register-resident weights, 2 seqs/block)
    lstm_kernel<<<NSEQ / 2, 256>>>(xg, w_hh, hfin);

    // head
    head_kernel<<<NSEQ, 128>>>(hfin, fc1_w, fc1_b, fc2_w, fc2_b, out);
}

// round 7
// speedup vs baseline: 1.5506x; 1.0410x over previous
#include <cuda_runtime.h>
#include <math.h>

// ---------------- problem constants ----------------
#define NTOT   102400          // B*T*NODES
#define ETOT   1638400         // edges
#define BATCH  8
#define TSTEPS 32
#define NODES  400
#define NSEQ   (BATCH*NODES)   // 3200
#define D_IN   64
#define L1F    96
#define L2F    64
#define GATES  256             // 4*64
#define FC1F   128
#define FC2F   3

// ---------------- device scratch (static: allowed) ----------------
__device__ float g_colsum[64];
__device__ float g_colsumsq[64];
__device__ float g_mean[64];
__device__ float g_rstd[64];
__device__ int   g_counts[NTOT];
__device__ int   g_rowptr[NTOT + 1];
__device__ int   g_cursor[NTOT];
__device__ int   g_bsums[128];
__device__ float g_deg[NTOT];
__device__ float g_dis[NTOT];
__device__ int   g_csrsrc[ETOT];
__device__ float g_csrw[ETOT];
__device__ __align__(16) float g_aggx [(size_t)NTOT * D_IN];
__device__ __align__(16) float g_h1   [(size_t)NTOT * L1F];
__device__ __align__(16) float g_h2pre[(size_t)NTOT * L2F];
__device__ __align__(16) float g_h2   [(size_t)NTOT * L2F];
__device__ __align__(16) float g_xg   [(size_t)NTOT * GATES];
__device__ float g_hfin [(size_t)NSEQ * L2F];

// ---------------- init ----------------
__global__ void init_kernel() {
    int gid = blockIdx.x * blockDim.x + threadIdx.x;
    if (gid < NTOT) { g_counts[gid] = 0; g_deg[gid] = 1.0f; }
    if (gid < 64)   { g_colsum[gid] = 0.f; g_colsumsq[gid] = 0.f; }
}

// ---------------- column stats (mean/std, ddof=1) ----------------
__global__ void col_stats_kernel(const float* __restrict__ x) {
    __shared__ float ssum[256], ssq[256];
    int c  = threadIdx.x & 63;
    int rr = threadIdx.x >> 6;
    float s = 0.f, q = 0.f;
    for (int row = blockIdx.x * 4 + rr; row < NTOT; row += gridDim.x * 4) {
        float v = x[(size_t)row * 64 + c];
        s += v; q += v * v;
    }
    ssum[threadIdx.x] = s; ssq[threadIdx.x] = q;
    __syncthreads();
    if (threadIdx.x < 64) {
        float S = ssum[threadIdx.x] + ssum[threadIdx.x + 64] + ssum[threadIdx.x + 128] + ssum[threadIdx.x + 192];
        float Q = ssq [threadIdx.x] + ssq [threadIdx.x + 64] + ssq [threadIdx.x + 128] + ssq [threadIdx.x + 192];
        atomicAdd(&g_colsum[threadIdx.x], S);
        atomicAdd(&g_colsumsq[threadIdx.x], Q);
    }
}

__global__ void stats_finalize_kernel() {
    int c = threadIdx.x;
    if (c < 64) {
        float n = (float)NTOT;
        float mean = g_colsum[c] / n;
        float var  = (g_colsumsq[c] - n * mean * mean) / (n - 1.0f);
        g_mean[c] = mean;
        g_rstd[c] = rsqrtf(var);
    }
}

// ---------------- edge pass 1: histogram + weighted degree ----------------
__global__ void edge_pass1_kernel(const int* __restrict__ ei, const float* __restrict__ ea) {
    int e = blockIdx.x * blockDim.x + threadIdx.x;
    if (e >= ETOT) return;
    int dst = ei[ETOT + e];
    float w = fabsf(((const float2*)ea)[e].x);
    atomicAdd(&g_counts[dst], 1);
    atomicAdd(&g_deg[dst], w);
}

// ---------------- scan (exclusive) over counts ----------------
__global__ void scan1_kernel() {
    __shared__ int tmp[1024];
    int gid = blockIdx.x * 1024 + threadIdx.x;
    int v = g_counts[gid];
    tmp[threadIdx.x] = v;
    __syncthreads();
    int val = v;
    for (int off = 1; off < 1024; off <<= 1) {
        int add = (threadIdx.x >= off) ? tmp[threadIdx.x - off] : 0;
        __syncthreads();
        val += add;
        tmp[threadIdx.x] = val;
        __syncthreads();
    }
    g_rowptr[gid] = val - v;           // exclusive, local to block
    if (threadIdx.x == 1023) g_bsums[blockIdx.x] = val;
}

__global__ void scan2_kernel() {
    __shared__ int tmp[128];
    int t = threadIdx.x;
    int v = (t < NTOT / 1024) ? g_bsums[t] : 0;
    tmp[t] = v;
    __syncthreads();
    int val = v;
    for (int off = 1; off < 128; off <<= 1) {
        int add = (t >= off) ? tmp[t - off] : 0;
        __syncthreads();
        val += add;
        tmp[t] = val;
        __syncthreads();
    }
    if (t < NTOT / 1024) g_bsums[t] = val - v;   // exclusive
}

__global__ void scan3_kernel() {
    int gid = blockIdx.x * blockDim.x + threadIdx.x;
    if (gid >= NTOT) return;
    int rp = g_rowptr[gid] + g_bsums[gid >> 10];
    g_rowptr[gid] = rp;
    g_cursor[gid] = rp;
    g_dis[gid] = rsqrtf(g_deg[gid]);   // deg >= 1 always (self loop weight 1)
    if (gid == 0) g_rowptr[NTOT] = ETOT;
}

// ---------------- edge pass 2: scatter into CSR (weights pre-scaled by dis[src]) ----------------
__global__ void edge_scatter_kernel(const int* __restrict__ ei, const float* __restrict__ ea) {
    int e = blockIdx.x * blockDim.x + threadIdx.x;
    if (e >= ETOT) return;
    int dst = ei[ETOT + e];
    int src = ei[e];
    float w = fabsf(((const float2*)ea)[e].x) * g_dis[src];
    int pos = atomicAdd(&g_cursor[dst], 1);
    g_csrsrc[pos] = src;
    g_csrw[pos] = w;
}

// ---------------- high-intensity tiled SGEMM ----------------
// C[M,Nout] = A[M,K] @ B (+bias)(+bias2)[+relu].  BM=128, BN in {64,96}, BK=16.
// Thread tile 8x4; threads = (BN/4)*16.  3 LDS.128 per 32 FFMA -> FFMA-bound.
// Tiles divide exactly (M%128==0, Nout%BN==0, K%16==0): no bounds checks.
template<int BN, bool TRANSB, bool RELU>
__global__ void gemm128_kernel(const float* __restrict__ A, const float* __restrict__ Bm,
                               const float* __restrict__ bias, const float* __restrict__ bias2,
                               float* __restrict__ C, int K, int Nout) {
    constexpr int TX = BN / 4;          // threads along n
    constexpr int THREADS = TX * 16;
    __shared__ __align__(16) float As[16][132];
    __shared__ __align__(16) float Bs[16][BN + 4];
    int tid = threadIdx.x;
    int m0 = blockIdx.x * 128, n0 = blockIdx.y * BN;
    int tx = tid % TX;                  // n-tile index (4 cols)
    int ty = tid / TX;                  // m-tile index (8 rows)

    float acc[8][4];
    #pragma unroll
    for (int i = 0; i < 8; i++)
        #pragma unroll
        for (int j = 0; j < 4; j++) acc[i][j] = 0.f;

    for (int k0 = 0; k0 < K; k0 += 16) {
        // A tile: 128 rows x 16 k  (512 float4), stored k-major
        #pragma unroll
        for (int idx = tid; idx < 512; idx += THREADS) {
            int r = idx >> 2, c4 = (idx & 3) * 4;
            float4 a = *(const float4*)(A + (size_t)(m0 + r) * K + k0 + c4);
            As[c4][r] = a.x; As[c4 + 1][r] = a.y; As[c4 + 2][r] = a.z; As[c4 + 3][r] = a.w;
        }
        // B tile: 16 k x BN n
        if (!TRANSB) {
            #pragma unroll
            for (int idx = tid; idx < 16 * TX; idx += THREADS) {
                int r = idx / TX, c = (idx % TX) * 4;
                float4 b = *(const float4*)(Bm + (size_t)(k0 + r) * Nout + n0 + c);
                Bs[r][c] = b.x; Bs[r][c + 1] = b.y; Bs[r][c + 2] = b.z; Bs[r][c + 3] = b.w;
            }
        } else {
            #pragma unroll
            for (int idx = tid; idx < BN * 4; idx += THREADS) {
                int c = idx % BN, r4 = (idx / BN) * 4;
                float4 b = *(const float4*)(Bm + (size_t)(n0 + c) * K + k0 + r4);
                Bs[r4][c] = b.x; Bs[r4 + 1][c] = b.y; Bs[r4 + 2][c] = b.z; Bs[r4 + 3][c] = b.w;
            }
        }
        __syncthreads();
        #pragma unroll
        for (int kk = 0; kk < 16; kk++) {
            float4 a0 = *(const float4*)&As[kk][ty * 8];
            float4 a1 = *(const float4*)&As[kk][ty * 8 + 4];
            float4 b  = *(const float4*)&Bs[kk][tx * 4];
            acc[0][0] += a0.x * b.x; acc[0][1] += a0.x * b.y; acc[0][2] += a0.x * b.z; acc[0][3] += a0.x * b.w;
            acc[1][0] += a0.y * b.x; acc[1][1] += a0.y * b.y; acc[1][2] += a0.y * b.z; acc[1][3] += a0.y * b.w;
            acc[2][0] += a0.z * b.x; acc[2][1] += a0.z * b.y; acc[2][2] += a0.z * b.z; acc[2][3] += a0.z * b.w;
            acc[3][0] += a0.w * b.x; acc[3][1] += a0.w * b.y; acc[3][2] += a0.w * b.z; acc[3][3] += a0.w * b.w;
            acc[4][0] += a1.x * b.x; acc[4][1] += a1.x * b.y; acc[4][2] += a1.x * b.z; acc[4][3] += a1.x * b.w;
            acc[5][0] += a1.y * b.x; acc[5][1] += a1.y * b.y; acc[5][2] += a1.y * b.z; acc[5][3] += a1.y * b.w;
            acc[6][0] += a1.z * b.x; acc[6][1] += a1.z * b.y; acc[6][2] += a1.z * b.z; acc[6][3] += a1.z * b.w;
            acc[7][0] += a1.w * b.x; acc[7][1] += a1.w * b.y; acc[7][2] += a1.w * b.z; acc[7][3] += a1.w * b.w;
        }
        __syncthreads();
    }

    int n = n0 + tx * 4;
    float bx = 0.f, by = 0.f, bz = 0.f, bw = 0.f;
    if (bias)  { bx += bias[n];  by += bias[n + 1];  bz += bias[n + 2];  bw += bias[n + 3]; }
    if (bias2) { bx += bias2[n]; by += bias2[n + 1]; bz += bias2[n + 2]; bw += bias2[n + 3]; }
    #pragma unroll
    for (int i = 0; i < 8; i++) {
        int m = m0 + ty * 8 + i;
        float4 v = make_float4(acc[i][0] + bx, acc[i][1] + by, acc[i][2] + bz, acc[i][3] + bw);
        if (RELU) { v.x = fmaxf(v.x, 0.f); v.y = fmaxf(v.y, 0.f); v.z = fmaxf(v.z, 0.f); v.w = fmaxf(v.w, 0.f); }
        *(float4*)(C + (size_t)m * Nout + n) = v;
    }
}

// ---------------- conv1 aggregation over RAW x, normalization folded into epilogue ----------------
// aggx_i[c] = r[c]*( di*S[c] + di^2*x_i[c] - (di*W + di^2)*m[c] ),  S=sum wd_j*x_j, W=sum wd_j
__global__ void agg_x_kernel(const float* __restrict__ x, float* __restrict__ out) {
    int warpId = (blockIdx.x * blockDim.x + threadIdx.x) >> 5;
    int lane = threadIdx.x & 31;
    if (warpId >= NTOT) return;
    int i = warpId;
    int beg = g_rowptr[i], end = g_rowptr[i + 1];
    float di = g_dis[i];
    float acc0 = 0.f, acc1 = 0.f, wsum = 0.f;

    for (int e0 = beg; e0 < end; e0 += 32) {
        int cnt = min(32, end - e0);
        int s_l = i; float w_l = 0.f;               // padding lanes: weight 0
        if (lane < cnt) {
            s_l = g_csrsrc[e0 + lane];
            w_l = g_csrw[e0 + lane];                // pre-scaled by dis[src]
        }
        for (int j = 0; j < cnt; j += 4) {
            int   s0 = __shfl_sync(0xffffffffu, s_l, j);
            int   s1 = __shfl_sync(0xffffffffu, s_l, j + 1);
            int   s2 = __shfl_sync(0xffffffffu, s_l, j + 2);
            int   s3 = __shfl_sync(0xffffffffu, s_l, j + 3);
            float w0 = __shfl_sync(0xffffffffu, w_l, j);
            float w1 = __shfl_sync(0xffffffffu, w_l, j + 1);
            float w2 = __shfl_sync(0xffffffffu, w_l, j + 2);
            float w3 = __shfl_sync(0xffffffffu, w_l, j + 3);
            const float* r0 = x + (size_t)s0 * 64 + lane;
            const float* r1 = x + (size_t)s1 * 64 + lane;
            const float* r2 = x + (size_t)s2 * 64 + lane;
            const float* r3 = x + (size_t)s3 * 64 + lane;
            float a0 = r0[0],  a1 = r1[0],  a2 = r2[0],  a3 = r3[0];
            float b0 = r0[32], b1 = r1[32], b2 = r2[32], b3 = r3[32];
            acc0 += a0 * w0 + a1 * w1 + a2 * w2 + a3 * w3;
            acc1 += b0 * w0 + b1 * w1 + b2 * w2 + b3 * w3;
            wsum += w0 + w1 + w2 + w3;
        }
    }
    float di2 = di * di;
    float coef = di * wsum + di2;
    float xi0 = x[(size_t)i * 64 + lane];
    float xi1 = x[(size_t)i * 64 + lane + 32];
    out[(size_t)i * 64 + lane]      = g_rstd[lane]      * (di * acc0 + di2 * xi0 - coef * g_mean[lane]);
    out[(size_t)i * 64 + lane + 32] = g_rstd[lane + 32] * (di * acc1 + di2 * xi1 - coef * g_mean[lane + 32]);
}

// ---------------- GCN aggregation (conv2): one warp per dst node, bias+relu epilogue ----------------
template<int F>
__global__ void agg_kernel(const float* __restrict__ hpre, const float* __restrict__ bias,
                           float* __restrict__ out) {
    int warpId = (blockIdx.x * blockDim.x + threadIdx.x) >> 5;
    int lane = threadIdx.x & 31;
    if (warpId >= NTOT) return;
    const int R = F / 32;
    int i = warpId;
    int beg = g_rowptr[i], end = g_rowptr[i + 1];
    float di = g_dis[i];
    float acc[R];
    #pragma unroll
    for (int r = 0; r < R; r++) acc[r] = 0.f;

    for (int e0 = beg; e0 < end; e0 += 32) {
        int cnt = min(32, end - e0);
        int s_l = i; float w_l = 0.f;
        if (lane < cnt) {
            s_l = g_csrsrc[e0 + lane];
            w_l = g_csrw[e0 + lane];                // pre-scaled by dis[src]
        }
        for (int j = 0; j < cnt; j += 4) {
            int   s0 = __shfl_sync(0xffffffffu, s_l, j);
            int   s1 = __shfl_sync(0xffffffffu, s_l, j + 1);
            int   s2 = __shfl_sync(0xffffffffu, s_l, j + 2);
            int   s3 = __shfl_sync(0xffffffffu, s_l, j + 3);
            float w0 = __shfl_sync(0xffffffffu, w_l, j);
            float w1 = __shfl_sync(0xffffffffu, w_l, j + 1);
            float w2 = __shfl_sync(0xffffffffu, w_l, j + 2);
            float w3 = __shfl_sync(0xffffffffu, w_l, j + 3);
            const float* r0 = hpre + (size_t)s0 * F + lane;
            const float* r1 = hpre + (size_t)s1 * F + lane;
            const float* r2 = hpre + (size_t)s2 * F + lane;
            const float* r3 = hpre + (size_t)s3 * F + lane;
            float v0[R], v1[R], v2[R], v3[R];
            #pragma unroll
            for (int r = 0; r < R; r++) { v0[r] = r0[32 * r]; v1[r] = r1[32 * r]; v2[r] = r2[32 * r]; v3[r] = r3[32 * r]; }
            #pragma unroll
            for (int r = 0; r < R; r++)
                acc[r] += v0[r] * w0 + v1[r] * w1 + v2[r] * w2 + v3[r] * w3;
        }
    }
    const float* self = hpre + (size_t)i * F;
    #pragma unroll
    for (int r = 0; r < R; r++) {
        float v = acc[r] * di + self[lane + 32 * r] * di * di + bias[lane + 32 * r];
        out[(size_t)i * F + lane + 32 * r] = fmaxf(v, 0.f);
    }
}

// ---------------- LSTM: register-resident weights ----------------
__device__ __forceinline__ float sigm(float x) { return 1.0f / (1.0f + expf(-x)); }

__global__ __launch_bounds__(256) void lstm_kernel(const float* __restrict__ xg,
                                                   const float* __restrict__ w_hh,
                                                   float* __restrict__ hfinal) {
    __shared__ float  h_sm[2][64];
    __shared__ __align__(16) float4 p_sm[2][4][64];
    int t = threadIdx.x;
    int j = t & 63, kc = t >> 6;
    int k0 = kc * 16;

    float wI[16], wF[16], wG[16], wO[16];
    #pragma unroll
    for (int kk = 0; kk < 16; kk++) {
        wI[kk] = w_hh[(size_t)(      j) * 64 + k0 + kk];
        wF[kk] = w_hh[(size_t)( 64 + j) * 64 + k0 + kk];
        wG[kk] = w_hh[(size_t)(128 + j) * 64 + k0 + kk];
        wO[kk] = w_hh[(size_t)(192 + j) * 64 + k0 + kk];
    }
    int seq0 = blockIdx.x * 2;
    int bA = seq0 / NODES,       nA = seq0 % NODES;
    int bB = (seq0 + 1) / NODES, nB = (seq0 + 1) % NODES;

    float c_state = 0.f;
    if (t < 128) h_sm[kc][j] = 0.f;
    __syncthreads();

    for (int step = 0; step < TSTEPS; step++) {
        float ai = 0.f, af = 0.f, ag = 0.f, ao = 0.f;
        float bi = 0.f, bf = 0.f, bg = 0.f, bo = 0.f;
        #pragma unroll
        for (int kk = 0; kk < 16; kk++) {
            float h0 = h_sm[0][k0 + kk];
            float h1 = h_sm[1][k0 + kk];
            ai += h0 * wI[kk]; af += h0 * wF[kk]; ag += h0 * wG[kk]; ao += h0 * wO[kk];
            bi += h1 * wI[kk]; bf += h1 * wF[kk]; bg += h1 * wG[kk]; bo += h1 * wO[kk];
        }
        p_sm[0][kc][j] = make_float4(ai, af, ag, ao);
        p_sm[1][kc][j] = make_float4(bi, bf, bg, bo);
        __syncthreads();
        if (t < 128) {
            int s = kc;
            int bb = s ? bB : bA, nn = s ? nB : nA;
            size_t row = ((size_t)(bb * TSTEPS + step) * NODES + nn) * GATES;
            float4 p = p_sm[s][0][j];
            float4 q = p_sm[s][1][j];
            float4 r = p_sm[s][2][j];
            float4 w = p_sm[s][3][j];
            float gi = p.x + q.x + r.x + w.x + xg[row + j];
            float gf = p.y + q.y + r.y + w.y + xg[row + 64 + j];
            float gg = p.z + q.z + r.z + w.z + xg[row + 128 + j];
            float go = p.w + q.w + r.w + w.w + xg[row + 192 + j];
            c_state = sigm(gf) * c_state + sigm(gi) * tanhf(gg);
            h_sm[s][j] = sigm(go) * tanhf(c_state);
        }
        __syncthreads();
    }
    if (t < 128) hfinal[(size_t)(seq0 + kc) * 64 + j] = h_sm[kc][j];
}

// ---------------- head: fc1 + relu + fc2 + softmax ----------------
__global__ void head_kernel(const float* __restrict__ hfinal,
                            const float* __restrict__ fc1_w, const float* __restrict__ fc1_b,
                            const float* __restrict__ fc2_w, const float* __restrict__ fc2_b,
                            float* __restrict__ out) {
    __shared__ float h[64];
    __shared__ float f1[128];
    __shared__ float logits[3];
    int s = blockIdx.x, tid = threadIdx.x;
    if (tid < 64) h[tid] = hfinal[(size_t)s * 64 + tid];
    __syncthreads();
    float acc = fc1_b[tid];
    #pragma unroll 8
    for (int k = 0; k < 64; k++) acc += h[k] * fc1_w[(size_t)tid * 64 + k];
    f1[tid] = fmaxf(acc, 0.f);
    __syncthreads();
    if (tid < 3) {
        float l = fc2_b[tid];
        #pragma unroll 8
        for (int k = 0; k < 128; k++) l += f1[k] * fc2_w[(size_t)tid * 128 + k];
        logits[tid] = l;
    }
    __syncthreads();
    if (tid == 0) {
        float m = fmaxf(logits[0], fmaxf(logits[1], logits[2]));
        float e0 = expf(logits[0] - m), e1 = expf(logits[1] - m), e2 = expf(logits[2] - m);
        float inv = 1.0f / (e0 + e1 + e2);
        out[(size_t)s * 3 + 0] = e0 * inv;
        out[(size_t)s * 3 + 1] = e1 * inv;
        out[(size_t)s * 3 + 2] = e2 * inv;
    }
}

// ---------------- host launcher ----------------
static void* sym_addr(const void* sym) {
    void* p = nullptr;
    cudaGetSymbolAddress(&p, sym);
    return p;
}

extern "C" void kernel_launch(void* const* d_in, const int* in_sizes, int n_in,
                              void* d_out, int out_size) {
    const float* x        = (const float*)d_in[0];
    const float* ea       = (const float*)d_in[1];
    const float* conv1_w  = (const float*)d_in[2];
    const float* conv1_b  = (const float*)d_in[3];
    const float* conv2_w  = (const float*)d_in[4];
    const float* conv2_b  = (const float*)d_in[5];
    const float* w_ih     = (const float*)d_in[6];
    const float* w_hh     = (const float*)d_in[7];
    const float* b_ih     = (const float*)d_in[8];
    const float* b_hh     = (const float*)d_in[9];
    const float* fc1_w    = (const float*)d_in[10];
    const float* fc1_b    = (const float*)d_in[11];
    const float* fc2_w    = (const float*)d_in[12];
    const float* fc2_b    = (const float*)d_in[13];
    const int*   ei       = (const int*)d_in[14];
    float* out = (float*)d_out;

    float* aggx  = (float*)sym_addr(g_aggx);
    float* h1    = (float*)sym_addr(g_h1);
    float* h2pre = (float*)sym_addr(g_h2pre);
    float* h2    = (float*)sym_addr(g_h2);
    float* xg    = (float*)sym_addr(g_xg);
    float* hfin  = (float*)sym_addr(g_hfin);

    // stats + graph structure
    init_kernel<<<(NTOT + 255) / 256, 256>>>();
    col_stats_kernel<<<200, 256>>>(x);
    stats_finalize_kernel<<<1, 64>>>();
    edge_pass1_kernel<<<ETOT / 256, 256>>>(ei, ea);
    scan1_kernel<<<NTOT / 1024, 1024>>>();
    scan2_kernel<<<1, 128>>>();
    scan3_kernel<<<(NTOT + 255) / 256, 256>>>();
    edge_scatter_kernel<<<ETOT / 256, 256>>>(ei, ea);

    // conv1 (reordered): aggx = agg(norm(x));  h1 = relu(aggx @ W1 + b1)
    agg_x_kernel<<<NTOT / 8, 256>>>(x, aggx);
    gemm128_kernel<96, false, true><<<dim3(NTOT / 128, 1), 384>>>(aggx, conv1_w, conv1_b, nullptr, h1, 64, L1F);

    // conv2: h2 = relu(agg(h1 @ W2) + b2)
    gemm128_kernel<64, false, false><<<dim3(NTOT / 128, 1), 256>>>(h1, conv2_w, nullptr, nullptr, h2pre, 96, L2F);
    agg_kernel<L2F><<<NTOT / 8, 256>>>(h2pre, conv2_b, h2);

    // LSTM input projection: xg = h2 @ w_ih^T + (b_ih + b_hh)
    gemm128_kernel<64, true, false><<<dim3(NTOT / 128, 4), 256>>>(h2, w_ih, b_ih, b_hh, xg, 64, GATES);

    // recurrence (register-resident weights, 2 seqs/block)
    lstm_kernel<<<NSEQ / 2, 256>>>(xg, w_hh, hfin);

    // head
    head_kernel<<<NSEQ, 128>>>(hfin, fc1_w, fc1_b, fc2_w, fc2_b, out);
}

// round 8
// speedup vs baseline: 1.6218x; 1.0459x over previous
#include <cuda_runtime.h>
#include <math.h>

// ---------------- problem constants ----------------
#define NTOT   102400          // B*T*NODES
#define ETOT   1638400         // edges
#define BATCH  8
#define TSTEPS 32
#define NODES  400
#define NSEQ   (BATCH*NODES)   // 3200
#define D_IN   64
#define L1F    96
#define L2F    64
#define GATES  256             // 4*64
#define FC1F   128
#define FC2F   3

// ---------------- device scratch (static: allowed) ----------------
__device__ float g_colsum[64];
__device__ float g_colsumsq[64];
__device__ float g_mean[64];
__device__ float g_rstd[64];
__device__ int   g_counts[NTOT];
__device__ int   g_rowptr[NTOT + 1];
__device__ int   g_cursor[NTOT];
__device__ int   g_bsums[128];
__device__ float g_deg[NTOT];
__device__ float g_dis[NTOT];
__device__ __align__(16) int2  g_csr[ETOT];          // {src, float_bits(w*dis[src])}
__device__ __align__(16) float g_aggx [(size_t)NTOT * D_IN];
__device__ __align__(16) float g_h1   [(size_t)NTOT * L1F];
__device__ __align__(16) float g_h2pre[(size_t)NTOT * L2F];
__device__ __align__(16) float g_h2   [(size_t)NTOT * L2F];
__device__ __align__(16) float g_xg   [(size_t)NTOT * GATES];
__device__ float g_hfin [(size_t)NSEQ * L2F];

// ---------------- init ----------------
__global__ void init_kernel() {
    int gid = blockIdx.x * blockDim.x + threadIdx.x;
    if (gid < NTOT) { g_counts[gid] = 0; g_deg[gid] = 1.0f; }
    if (gid < 64)   { g_colsum[gid] = 0.f; g_colsumsq[gid] = 0.f; }
}

// ---------------- column stats (mean/std, ddof=1) ----------------
__global__ void col_stats_kernel(const float* __restrict__ x) {
    __shared__ float ssum[256], ssq[256];
    int c  = threadIdx.x & 63;
    int rr = threadIdx.x >> 6;
    float s = 0.f, q = 0.f;
    for (int row = blockIdx.x * 4 + rr; row < NTOT; row += gridDim.x * 4) {
        float v = x[(size_t)row * 64 + c];
        s += v; q += v * v;
    }
    ssum[threadIdx.x] = s; ssq[threadIdx.x] = q;
    __syncthreads();
    if (threadIdx.x < 64) {
        float S = ssum[threadIdx.x] + ssum[threadIdx.x + 64] + ssum[threadIdx.x + 128] + ssum[threadIdx.x + 192];
        float Q = ssq [threadIdx.x] + ssq [threadIdx.x + 64] + ssq [threadIdx.x + 128] + ssq [threadIdx.x + 192];
        atomicAdd(&g_colsum[threadIdx.x], S);
        atomicAdd(&g_colsumsq[threadIdx.x], Q);
    }
}

__global__ void stats_finalize_kernel() {
    int c = threadIdx.x;
    if (c < 64) {
        float n = (float)NTOT;
        float mean = g_colsum[c] / n;
        float var  = (g_colsumsq[c] - n * mean * mean) / (n - 1.0f);
        g_mean[c] = mean;
        g_rstd[c] = rsqrtf(var);
    }
}

// ---------------- edge pass 1: histogram + weighted degree ----------------
__global__ void edge_pass1_kernel(const int* __restrict__ ei, const float* __restrict__ ea) {
    int e = blockIdx.x * blockDim.x + threadIdx.x;
    if (e >= ETOT) return;
    int dst = ei[ETOT + e];
    float w = fabsf(((const float2*)ea)[e].x);
    atomicAdd(&g_counts[dst], 1);
    atomicAdd(&g_deg[dst], w);
}

// ---------------- scan (exclusive) over counts ----------------
__global__ void scan1_kernel() {
    __shared__ int tmp[1024];
    int gid = blockIdx.x * 1024 + threadIdx.x;
    int v = g_counts[gid];
    tmp[threadIdx.x] = v;
    __syncthreads();
    int val = v;
    for (int off = 1; off < 1024; off <<= 1) {
        int add = (threadIdx.x >= off) ? tmp[threadIdx.x - off] : 0;
        __syncthreads();
        val += add;
        tmp[threadIdx.x] = val;
        __syncthreads();
    }
    g_rowptr[gid] = val - v;           // exclusive, local to block
    if (threadIdx.x == 1023) g_bsums[blockIdx.x] = val;
}

__global__ void scan2_kernel() {
    __shared__ int tmp[128];
    int t = threadIdx.x;
    int v = (t < NTOT / 1024) ? g_bsums[t] : 0;
    tmp[t] = v;
    __syncthreads();
    int val = v;
    for (int off = 1; off < 128; off <<= 1) {
        int add = (t >= off) ? tmp[t - off] : 0;
        __syncthreads();
        val += add;
        tmp[t] = val;
        __syncthreads();
    }
    if (t < NTOT / 1024) g_bsums[t] = val - v;   // exclusive
}

__global__ void scan3_kernel() {
    int gid = blockIdx.x * blockDim.x + threadIdx.x;
    if (gid >= NTOT) return;
    int rp = g_rowptr[gid] + g_bsums[gid >> 10];
    g_rowptr[gid] = rp;
    g_cursor[gid] = rp;
    g_dis[gid] = rsqrtf(g_deg[gid]);   // deg >= 1 always (self loop weight 1)
    if (gid == 0) g_rowptr[NTOT] = ETOT;
}

// ---------------- edge pass 2: scatter into CSR (packed int2, w pre-scaled by dis[src]) ----------------
__global__ void edge_scatter_kernel(const int* __restrict__ ei, const float* __restrict__ ea) {
    int e = blockIdx.x * blockDim.x + threadIdx.x;
    if (e >= ETOT) return;
    int dst = ei[ETOT + e];
    int src = ei[e];
    float w = fabsf(((const float2*)ea)[e].x) * g_dis[src];
    int pos = atomicAdd(&g_cursor[dst], 1);
    g_csr[pos] = make_int2(src, __float_as_int(w));
}

// ---------------- panel-resident SGEMM ----------------
// C[M, BN*NTILES] = A[M,K] @ B (+bias)(+bias2)[+relu].  BM=128, whole K in smem.
// A panel loaded ONCE per block; B n-tiles looped (A reuse).  Thread tile 8x4.
// THREADS = (BN/4)*16.  All dims divide exactly: no bounds checks.
template<int K, int BN, int NTILES, bool TRANSB, bool RELU>
__global__ void gemmP_kernel(const float* __restrict__ A, const float* __restrict__ Bm,
                             const float* __restrict__ bias, const float* __restrict__ bias2,
                             float* __restrict__ C) {
    constexpr int Nout = BN * NTILES;
    constexpr int TX = BN / 4;
    constexpr int THREADS = TX * 16;
    constexpr int SA = 132;            // 132*4B multiple of 16 -> float4-aligned rows
    constexpr int SB = BN + 4;         // (BN+4)*4B multiple of 16
    extern __shared__ float smem[];
    float* sA = smem;                  // [K][SA]  (k-major)
    float* sB = smem + K * SA;         // [K][SB]

    int tid = threadIdx.x;
    int m0 = blockIdx.x * 128;
    int tx = tid % TX;
    int ty = tid / TX;

    // ---- load A panel once: 128 rows x K, transpose to k-major ----
    constexpr int NF4 = K / 4;
    for (int idx = tid; idx < 128 * NF4; idx += THREADS) {
        int r = idx / NF4, c4 = (idx % NF4) * 4;
        float4 a = *(const float4*)(A + (size_t)(m0 + r) * K + c4);
        sA[(c4    ) * SA + r] = a.x;
        sA[(c4 + 1) * SA + r] = a.y;
        sA[(c4 + 2) * SA + r] = a.z;
        sA[(c4 + 3) * SA + r] = a.w;
    }

    for (int nt = 0; nt < NTILES; nt++) {
        int n0 = nt * BN;
        __syncthreads();               // A panel ready (iter 0); Bs free of readers (iter>0)
        // ---- load B tile: K x BN ----
        if (!TRANSB) {
            constexpr int BF4 = BN / 4;
            for (int idx = tid; idx < K * BF4; idx += THREADS) {
                int r = idx / BF4, c = (idx % BF4) * 4;
                float4 b = *(const float4*)(Bm + (size_t)r * Nout + n0 + c);
                *(float4*)&sB[r * SB + c] = b;
            }
        } else {
            constexpr int KF4 = K / 4;
            for (int idx = tid; idx < BN * KF4; idx += THREADS) {
                int n = idx / KF4, k4 = (idx % KF4) * 4;
                float4 b = *(const float4*)(Bm + (size_t)(n0 + n) * K + k4);
                sB[(k4    ) * SB + n] = b.x;
                sB[(k4 + 1) * SB + n] = b.y;
                sB[(k4 + 2) * SB + n] = b.z;
                sB[(k4 + 3) * SB + n] = b.w;
            }
        }
        __syncthreads();

        float acc[8][4];
        #pragma unroll
        for (int i = 0; i < 8; i++)
            #pragma unroll
            for (int j = 0; j < 4; j++) acc[i][j] = 0.f;

        #pragma unroll 8
        for (int kk = 0; kk < K; kk++) {
            float4 a0 = *(const float4*)&sA[kk * SA + ty * 8];
            float4 a1 = *(const float4*)&sA[kk * SA + ty * 8 + 4];
            float4 b  = *(const float4*)&sB[kk * SB + tx * 4];
            acc[0][0] += a0.x * b.x; acc[0][1] += a0.x * b.y; acc[0][2] += a0.x * b.z; acc[0][3] += a0.x * b.w;
            acc[1][0] += a0.y * b.x; acc[1][1] += a0.y * b.y; acc[1][2] += a0.y * b.z; acc[1][3] += a0.y * b.w;
            acc[2][0] += a0.z * b.x; acc[2][1] += a0.z * b.y; acc[2][2] += a0.z * b.z; acc[2][3] += a0.z * b.w;
            acc[3][0] += a0.w * b.x; acc[3][1] += a0.w * b.y; acc[3][2] += a0.w * b.z; acc[3][3] += a0.w * b.w;
            acc[4][0] += a1.x * b.x; acc[4][1] += a1.x * b.y; acc[4][2] += a1.x * b.z; acc[4][3] += a1.x * b.w;
            acc[5][0] += a1.y * b.x; acc[5][1] += a1.y * b.y; acc[5][2] += a1.y * b.z; acc[5][3] += a1.y * b.w;
            acc[6][0] += a1.z * b.x; acc[6][1] += a1.z * b.y; acc[6][2] += a1.z * b.z; acc[6][3] += a1.z * b.w;
            acc[7][0] += a1.w * b.x; acc[7][1] += a1.w * b.y; acc[7][2] += a1.w * b.z; acc[7][3] += a1.w * b.w;
        }

        int n = n0 + tx * 4;
        float bx = 0.f, by = 0.f, bz = 0.f, bw = 0.f;
        if (bias)  { bx += bias[n];  by += bias[n + 1];  bz += bias[n + 2];  bw += bias[n + 3]; }
        if (bias2) { bx += bias2[n]; by += bias2[n + 1]; bz += bias2[n + 2]; bw += bias2[n + 3]; }
        #pragma unroll
        for (int i = 0; i < 8; i++) {
            int m = m0 + ty * 8 + i;
            float4 v = make_float4(acc[i][0] + bx, acc[i][1] + by, acc[i][2] + bz, acc[i][3] + bw);
            if (RELU) { v.x = fmaxf(v.x, 0.f); v.y = fmaxf(v.y, 0.f); v.z = fmaxf(v.z, 0.f); v.w = fmaxf(v.w, 0.f); }
            *(float4*)(C + (size_t)m * Nout + n) = v;
        }
    }
}

// ---------------- conv1 aggregation over RAW x, normalization folded into epilogue ----------------
__global__ void agg_x_kernel(const float* __restrict__ x, float* __restrict__ out) {
    int warpId = (blockIdx.x * blockDim.x + threadIdx.x) >> 5;
    int lane = threadIdx.x & 31;
    if (warpId >= NTOT) return;
    int i = warpId;
    int beg = g_rowptr[i], end = g_rowptr[i + 1];
    float di = g_dis[i];
    float acc0 = 0.f, acc1 = 0.f, wsum = 0.f;

    for (int e0 = beg; e0 < end; e0 += 32) {
        int cnt = min(32, end - e0);
        int s_l = i; float w_l = 0.f;
        if (lane < cnt) {
            int2 v = g_csr[e0 + lane];
            s_l = v.x;
            w_l = __int_as_float(v.y);
        }
        for (int j = 0; j < cnt; j += 4) {
            int   s0 = __shfl_sync(0xffffffffu, s_l, j);
            int   s1 = __shfl_sync(0xffffffffu, s_l, j + 1);
            int   s2 = __shfl_sync(0xffffffffu, s_l, j + 2);
            int   s3 = __shfl_sync(0xffffffffu, s_l, j + 3);
            float w0 = __shfl_sync(0xffffffffu, w_l, j);
            float w1 = __shfl_sync(0xffffffffu, w_l, j + 1);
            float w2 = __shfl_sync(0xffffffffu, w_l, j + 2);
            float w3 = __shfl_sync(0xffffffffu, w_l, j + 3);
            const float* r0 = x + (size_t)s0 * 64 + lane;
            const float* r1 = x + (size_t)s1 * 64 + lane;
            const float* r2 = x + (size_t)s2 * 64 + lane;
            const float* r3 = x + (size_t)s3 * 64 + lane;
            float a0 = r0[0],  a1 = r1[0],  a2 = r2[0],  a3 = r3[0];
            float b0 = r0[32], b1 = r1[32], b2 = r2[32], b3 = r3[32];
            acc0 += a0 * w0 + a1 * w1 + a2 * w2 + a3 * w3;
            acc1 += b0 * w0 + b1 * w1 + b2 * w2 + b3 * w3;
            wsum += w0 + w1 + w2 + w3;
        }
    }
    float di2 = di * di;
    float coef = di * wsum + di2;
    float xi0 = x[(size_t)i * 64 + lane];
    float xi1 = x[(size_t)i * 64 + lane + 32];
    out[(size_t)i * 64 + lane]      = g_rstd[lane]      * (di * acc0 + di2 * xi0 - coef * g_mean[lane]);
    out[(size_t)i * 64 + lane + 32] = g_rstd[lane + 32] * (di * acc1 + di2 * xi1 - coef * g_mean[lane + 32]);
}

// ---------------- GCN aggregation (conv2): one warp per dst node, bias+relu epilogue ----------------
template<int F>
__global__ void agg_kernel(const float* __restrict__ hpre, const float* __restrict__ bias,
                           float* __restrict__ out) {
    int warpId = (blockIdx.x * blockDim.x + threadIdx.x) >> 5;
    int lane = threadIdx.x & 31;
    if (warpId >= NTOT) return;
    const int R = F / 32;
    int i = warpId;
    int beg = g_rowptr[i], end = g_rowptr[i + 1];
    float di = g_dis[i];
    float acc[R];
    #pragma unroll
    for (int r = 0; r < R; r++) acc[r] = 0.f;

    for (int e0 = beg; e0 < end; e0 += 32) {
        int cnt = min(32, end - e0);
        int s_l = i; float w_l = 0.f;
        if (lane < cnt) {
            int2 v = g_csr[e0 + lane];
            s_l = v.x;
            w_l = __int_as_float(v.y);
        }
        for (int j = 0; j < cnt; j += 4) {
            int   s0 = __shfl_sync(0xffffffffu, s_l, j);
            int   s1 = __shfl_sync(0xffffffffu, s_l, j + 1);
            int   s2 = __shfl_sync(0xffffffffu, s_l, j + 2);
            int   s3 = __shfl_sync(0xffffffffu, s_l, j + 3);
            float w0 = __shfl_sync(0xffffffffu, w_l, j);
            float w1 = __shfl_sync(0xffffffffu, w_l, j + 1);
            float w2 = __shfl_sync(0xffffffffu, w_l, j + 2);
            float w3 = __shfl_sync(0xffffffffu, w_l, j + 3);
            const float* r0 = hpre + (size_t)s0 * F + lane;
            const float* r1 = hpre + (size_t)s1 * F + lane;
            const float* r2 = hpre + (size_t)s2 * F + lane;
            const float* r3 = hpre + (size_t)s3 * F + lane;
            float v0[R], v1[R], v2[R], v3[R];
            #pragma unroll
            for (int r = 0; r < R; r++) { v0[r] = r0[32 * r]; v1[r] = r1[32 * r]; v2[r] = r2[32 * r]; v3[r] = r3[32 * r]; }
            #pragma unroll
            for (int r = 0; r < R; r++)
                acc[r] += v0[r] * w0 + v1[r] * w1 + v2[r] * w2 + v3[r] * w3;
        }
    }
    const float* self = hpre + (size_t)i * F;
    #pragma unroll
    for (int r = 0; r < R; r++) {
        float v = acc[r] * di + self[lane + 32 * r] * di * di + bias[lane + 32 * r];
        out[(size_t)i * F + lane + 32 * r] = fmaxf(v, 0.f);
    }
}

// ---------------- LSTM: register-resident weights + xg prefetch ----------------
__device__ __forceinline__ float sigm(float x) { return 1.0f / (1.0f + expf(-x)); }

__global__ __launch_bounds__(256) void lstm_kernel(const float* __restrict__ xg,
                                                   const float* __restrict__ w_hh,
                                                   float* __restrict__ hfinal) {
    __shared__ float  h_sm[2][64];
    __shared__ __align__(16) float4 p_sm[2][4][64];
    int t = threadIdx.x;
    int j = t & 63, kc = t >> 6;
    int k0 = kc * 16;

    float wI[16], wF[16], wG[16], wO[16];
    #pragma unroll
    for (int kk = 0; kk < 16; kk++) {
        wI[kk] = w_hh[(size_t)(      j) * 64 + k0 + kk];
        wF[kk] = w_hh[(size_t)( 64 + j) * 64 + k0 + kk];
        wG[kk] = w_hh[(size_t)(128 + j) * 64 + k0 + kk];
        wO[kk] = w_hh[(size_t)(192 + j) * 64 + k0 + kk];
    }
    int seq0 = blockIdx.x * 2;
    int bA = seq0 / NODES,       nA = seq0 % NODES;
    int bB = (seq0 + 1) / NODES, nB = (seq0 + 1) % NODES;

    // reducer-thread sequence identity (threads t<128: s = kc)
    int bb = kc ? bB : bA, nn = kc ? nB : nA;

    float c_state = 0.f;
    float xi = 0.f, xf = 0.f, xgg = 0.f, xo = 0.f;
    if (t < 128) {
        h_sm[kc][j] = 0.f;
        size_t row0 = ((size_t)(bb * TSTEPS) * NODES + nn) * GATES;
        xi  = xg[row0 + j];
        xf  = xg[row0 + 64 + j];
        xgg = xg[row0 + 128 + j];
        xo  = xg[row0 + 192 + j];
    }
    __syncthreads();

    for (int step = 0; step < TSTEPS; step++) {
        float ai = 0.f, af = 0.f, ag = 0.f, ao = 0.f;
        float bi = 0.f, bf = 0.f, bg = 0.f, bo = 0.f;
        #pragma unroll
        for (int kk = 0; kk < 16; kk++) {
            float h0 = h_sm[0][k0 + kk];
            float h1 = h_sm[1][k0 + kk];
            ai += h0 * wI[kk]; af += h0 * wF[kk]; ag += h0 * wG[kk]; ao += h0 * wO[kk];
            bi += h1 * wI[kk]; bf += h1 * wF[kk]; bg += h1 * wG[kk]; bo += h1 * wO[kk];
        }
        p_sm[0][kc][j] = make_float4(ai, af, ag, ao);
        p_sm[1][kc][j] = make_float4(bi, bf, bg, bo);
        __syncthreads();
        if (t < 128) {
            // prefetch next step's gate inputs (hidden under reduce + activation + next FMA)
            float ni = 0.f, nf = 0.f, ng = 0.f, no = 0.f;
            if (step + 1 < TSTEPS) {
                size_t rown = ((size_t)(bb * TSTEPS + step + 1) * NODES + nn) * GATES;
                ni = xg[rown + j];
                nf = xg[rown + 64 + j];
                ng = xg[rown + 128 + j];
                no = xg[rown + 192 + j];
            }
            int s = kc;
            float4 p = p_sm[s][0][j];
            float4 q = p_sm[s][1][j];
            float4 r = p_sm[s][2][j];
            float4 w = p_sm[s][3][j];
            float gi = p.x + q.x + r.x + w.x + xi;
            float gf = p.y + q.y + r.y + w.y + xf;
            float gg = p.z + q.z + r.z + w.z + xgg;
            float go = p.w + q.w + r.w + w.w + xo;
            c_state = sigm(gf) * c_state + sigm(gi) * tanhf(gg);
            h_sm[s][j] = sigm(go) * tanhf(c_state);
            xi = ni; xf = nf; xgg = ng; xo = no;
        }
        __syncthreads();
    }
    if (t < 128) hfinal[(size_t)(seq0 + kc) * 64 + j] = h_sm[kc][j];
}

// ---------------- head: fc1 + relu + fc2 + softmax ----------------
__global__ void head_kernel(const float* __restrict__ hfinal,
                            const float* __restrict__ fc1_w, const float* __restrict__ fc1_b,
                            const float* __restrict__ fc2_w, const float* __restrict__ fc2_b,
                            float* __restrict__ out) {
    __shared__ float h[64];
    __shared__ float f1[128];
    __shared__ float logits[3];
    int s = blockIdx.x, tid = threadIdx.x;
    if (tid < 64) h[tid] = hfinal[(size_t)s * 64 + tid];
    __syncthreads();
    float acc = fc1_b[tid];
    #pragma unroll 8
    for (int k = 0; k < 64; k++) acc += h[k] * fc1_w[(size_t)tid * 64 + k];
    f1[tid] = fmaxf(acc, 0.f);
    __syncthreads();
    if (tid < 3) {
        float l = fc2_b[tid];
        #pragma unroll 8
        for (int k = 0; k < 128; k++) l += f1[k] * fc2_w[(size_t)tid * 128 + k];
        logits[tid] = l;
    }
    __syncthreads();
    if (tid == 0) {
        float m = fmaxf(logits[0], fmaxf(logits[1], logits[2]));
        float e0 = expf(logits[0] - m), e1 = expf(logits[1] - m), e2 = expf(logits[2] - m);
        float inv = 1.0f / (e0 + e1 + e2);
        out[(size_t)s * 3 + 0] = e0 * inv;
        out[(size_t)s * 3 + 1] = e1 * inv;
        out[(size_t)s * 3 + 2] = e2 * inv;
    }
}

// ---------------- host launcher ----------------
static void* sym_addr(const void* sym) {
    void* p = nullptr;
    cudaGetSymbolAddress(&p, sym);
    return p;
}

extern "C" void kernel_launch(void* const* d_in, const int* in_sizes, int n_in,
                              void* d_out, int out_size) {
    const float* x        = (const float*)d_in[0];
    const float* ea       = (const float*)d_in[1];
    const float* conv1_w  = (const float*)d_in[2];
    const float* conv1_b  = (const float*)d_in[3];
    const float* conv2_w  = (const float*)d_in[4];
    const float* conv2_b  = (const float*)d_in[5];
    const float* w_ih     = (const float*)d_in[6];
    const float* w_hh     = (const float*)d_in[7];
    const float* b_ih     = (const float*)d_in[8];
    const float* b_hh     = (const float*)d_in[9];
    const float* fc1_w    = (const float*)d_in[10];
    const float* fc1_b    = (const float*)d_in[11];
    const float* fc2_w    = (const float*)d_in[12];
    const float* fc2_b    = (const float*)d_in[13];
    const int*   ei       = (const int*)d_in[14];
    float* out = (float*)d_out;

    float* aggx  = (float*)sym_addr(g_aggx);
    float* h1    = (float*)sym_addr(g_h1);
    float* h2pre = (float*)sym_addr(g_h2pre);
    float* h2    = (float*)sym_addr(g_h2);
    float* xg    = (float*)sym_addr(g_xg);
    float* hfin  = (float*)sym_addr(g_hfin);

    // GEMM instantiations + smem sizes
    auto g1 = gemmP_kernel<64, 96, 1, false, true >;   // aggx@W1 (+b1, relu) -> h1
    auto g2 = gemmP_kernel<96, 64, 1, false, false>;   // h1@W2           -> h2pre
    auto g3 = gemmP_kernel<64, 64, 4, true,  false>;   // h2@w_ih^T (+b)  -> xg
    size_t s1 = (size_t)(64 * 132 + 64 * 100) * 4;     // 59392
    size_t s2 = (size_t)(96 * 132 + 96 * 68 ) * 4;     // 76800
    size_t s3 = (size_t)(64 * 132 + 64 * 68 ) * 4;     // 51200
    cudaFuncSetAttribute(g1, cudaFuncAttributeMaxDynamicSharedMemorySize, (int)s1);
    cudaFuncSetAttribute(g2, cudaFuncAttributeMaxDynamicSharedMemorySize, (int)s2);
    cudaFuncSetAttribute(g3, cudaFuncAttributeMaxDynamicSharedMemorySize, (int)s3);

    // stats + graph structure
    init_kernel<<<(NTOT + 255) / 256, 256>>>();
    col_stats_kernel<<<200, 256>>>(x);
    stats_finalize_kernel<<<1, 64>>>();
    edge_pass1_kernel<<<ETOT / 256, 256>>>(ei, ea);
    scan1_kernel<<<NTOT / 1024, 1024>>>();
    scan2_kernel<<<1, 128>>>();
    scan3_kernel<<<(NTOT + 255) / 256, 256>>>();
    edge_scatter_kernel<<<ETOT / 256, 256>>>(ei, ea);

    // conv1 (reordered): aggx = agg(norm(x));  h1 = relu(aggx @ W1 + b1)
    agg_x_kernel<<<NTOT / 8, 256>>>(x, aggx);
    g1<<<NTOT / 128, 384, s1>>>(aggx, conv1_w, conv1_b, nullptr, h1);

    // conv2: h2 = relu(agg(h1 @ W2) + b2)
    g2<<<NTOT / 128, 256, s2>>>(h1, conv2_w, nullptr, nullptr, h2pre);
    agg_kernel<L2F><<<NTOT / 8, 256>>>(h2pre, conv2_b, h2);

    // LSTM input projection: xg = h2 @ w_ih^T + (b_ih + b_hh)
    g3<<<NTOT / 128, 256, s3>>>(h2, w_ih, b_ih, b_hh, xg);

    // recurrence (register-resident weights, 2 seqs/block, xg prefetch)
    lstm_kernel<<<NSEQ / 2, 256>>>(xg, w_hh, hfin);

    // head
    head_kernel<<<NSEQ, 128>>>(hfin, fc1_w, fc1_b, fc2_w, fc2_b, out);
}